// round 6
// baseline (speedup 1.0000x reference)
#include <cuda_runtime.h>
#include <cuda_bf16.h>
#include <cstdint>

// ---------------------------------------------------------------------------
// EdgeAlignmentModule, single fused persistent kernel.
//
//   key(src,dst) = src * total_nodes + dst   (< 1e8, fits in uint32)
//   Slot word = (old_edge_idx << 32) | (key + 1).   0 == EMPTY.
//   Duplicate keys -> MAX old index (matches sequential scatter "last wins")
//   via atomicMax on the packed word (low 32 bits equal for equal keys).
//
// No reset pass: the table starts zeroed (module-load init) and each call
// zeroes exactly the slots it touched (recorded in g_slot) after all lookups
// complete, so every call begins with an empty table. Phases are separated
// by a software grid barrier (all 592 blocks are co-resident: 4 blocks/SM
// of 256 threads on 148 SMs).
// ---------------------------------------------------------------------------

#define TABLE_LOG2 20
#define TABLE_SIZE (1u << TABLE_LOG2)
#define TABLE_MASK (TABLE_SIZE - 1u)

#define NBLOCKS 592
#define NTHREADS 256
#define E_OLD_MAX 400000

__device__ unsigned long long g_tab[TABLE_SIZE];   // zero-init == all EMPTY
__device__ unsigned g_slot[E_OLD_MAX];             // slots touched this call
__device__ unsigned g_bar_count;                   // barrier arrivals (self-resets)
__device__ volatile unsigned g_bar_gen;            // barrier generation (monotonic)

__device__ __forceinline__ uint32_t hash_key(uint32_t key) {
    return (key * 0x9E3779B1u) >> (32 - TABLE_LOG2);
}

__device__ __forceinline__ void grid_barrier() {
    __syncthreads();
    if (threadIdx.x == 0) {
        unsigned gen = g_bar_gen;
        __threadfence();
        unsigned arrived = atomicAdd(&g_bar_count, 1u);
        if (arrived == NBLOCKS - 1) {
            g_bar_count = 0;           // reset for next barrier / next call
            __threadfence();
            g_bar_gen = gen + 1;       // release
        } else {
            while (g_bar_gen == gen) { }
        }
        __threadfence();
    }
    __syncthreads();
}

__global__ __launch_bounds__(NTHREADS, 4)
void edge_align_fused(const int*   __restrict__ edge_index_old,
                      const float* __restrict__ edge_attr_old,
                      const float* __restrict__ flow_old,
                      const int*   __restrict__ edge_index_new,
                      const float* __restrict__ edge_attr_new,
                      float*       __restrict__ out,
                      int E_old, int E_new, int total_nodes) {
    const int tid = blockIdx.x * NTHREADS + threadIdx.x;
    const int stride = NBLOCKS * NTHREADS;

    // ---- Phase 1: insert old edges, record touched slot per edge ----
    for (int i = tid; i < E_old; i += stride) {
        uint32_t key = (uint32_t)(__ldg(edge_index_old + i) * total_nodes
                                  + __ldg(edge_index_old + E_old + i));
        unsigned long long word =
            ((unsigned long long)(uint32_t)i << 32) | (key + 1u);

        uint32_t h = hash_key(key);
        while (true) {
            unsigned long long prev = atomicCAS(&g_tab[h], 0ull, word);
            if (prev == 0ull) break;                   // claimed slot + value
            if ((uint32_t)prev == key + 1u) {          // duplicate: max idx wins
                atomicMax(&g_tab[h], word);
                break;
            }
            h = (h + 1) & TABLE_MASK;
        }
        g_slot[i] = h;
    }

    grid_barrier();   // all inserts visible before any lookup

    // ---- Phase 2: lookup new edges, gather old feats, emit [E_new, 8] ----
    for (int i = tid; i < E_new; i += stride) {
        uint32_t key = (uint32_t)(__ldg(edge_index_new + i) * total_nodes
                                  + __ldg(edge_index_new + E_new + i));
        int match = -1;
        uint32_t h = hash_key(key);
        while (true) {
            unsigned long long w = __ldg(&g_tab[h]);
            if ((uint32_t)w == key + 1u) { match = (int)(w >> 32); break; }
            if (w == 0ull)               { break; }
            h = (h + 1) & TABLE_MASK;
        }

        float a0 = 0.f, a1 = 0.f, a2 = 0.f, a3 = 0.f;
        float flag = 1.f;  // is_new_edge
        if (match >= 0) {
            const float* ea = edge_attr_old + (size_t)match * 3;
            a0 = __ldg(ea + 0);
            a1 = __ldg(ea + 1);
            a2 = __ldg(ea + 2);
            a3 = __ldg(flow_old + match);
            flag = 0.f;
        }
        const float* en = edge_attr_new + (size_t)i * 3;
        float n0 = __ldg(en + 0), n1 = __ldg(en + 1), n2 = __ldg(en + 2);

        float4* o = reinterpret_cast<float4*>(out + (size_t)i * 8);
        o[0] = make_float4(a0, a1, a2, a3);
        o[1] = make_float4(n0, n1, n2, flag);
    }

    grid_barrier();   // all lookups done before the table is torn down

    // ---- Phase 3: cleanup — zero exactly the slots this call populated ----
    for (int i = tid; i < E_old; i += stride) {
        g_tab[g_slot[i]] = 0ull;
    }
}

extern "C" void kernel_launch(void* const* d_in, const int* in_sizes, int n_in,
                              void* d_out, int out_size) {
    const int*   edge_index_old = (const int*)  d_in[0];
    const float* edge_attr_old  = (const float*)d_in[1];
    const float* flow_old       = (const float*)d_in[2];
    const int*   edge_index_new = (const int*)  d_in[3];
    const float* edge_attr_new  = (const float*)d_in[4];
    (void)n_in; (void)out_size;

    int E_old = in_sizes[1] / 3;   // edge_attr_old is [E_old, 3]
    int E_new = in_sizes[4] / 3;   // edge_attr_new is [E_new, 3]
    int total_nodes = 10000;       // fixed by problem; key fits uint32

    edge_align_fused<<<NBLOCKS, NTHREADS>>>(edge_index_old, edge_attr_old,
                                            flow_old, edge_index_new,
                                            edge_attr_new, (float*)d_out,
                                            E_old, E_new, total_nodes);
}

// round 7
// speedup vs baseline: 1.2407x; 1.2407x over previous
#include <cuda_runtime.h>
#include <cuda_bf16.h>
#include <cstdint>

// ---------------------------------------------------------------------------
// EdgeAlignmentModule — generation-tagged hash join, 2 launches, no reset.
//
//   key(src,dst) = src * total_nodes + dst   (< 1e8, fits in 27 bits)
//   Slot word (64b) = gen(18) << 46 | key(27) << 19 | idx(19)
//
// A slot whose gen field != current call's gen is EMPTY (stale from an older
// call); it is claimed by CAS against the observed stale word. Duplicate keys
// within a call resolve to MAX old-edge index (== sequential-scatter "last
// wins" of table.at[old_keys].set(arange)) via atomicMax: for equal (gen,key)
// the word orders by idx.
//
// The per-call generation is computed on-device: each kernel owns a call
// counter; every block atomically bumps it once and derives
// gen = ctr / gridDim + 1. Stream ordering of launches partitions counter
// arrivals by call, so all blocks of one call observe the same gen, and the
// insert / lookup kernels (separate counters, one bump per call each) agree.
// Table starts zeroed (gen 0); first call uses gen 1. No reset, no cleanup.
// ---------------------------------------------------------------------------

#define TABLE_LOG2 20
#define TABLE_SIZE (1u << TABLE_LOG2)
#define TABLE_MASK (TABLE_SIZE - 1u)

#define GEN_SHIFT 46
#define KEY_SHIFT 19
#define IDX_MASK  ((1u << KEY_SHIFT) - 1u)

__device__ unsigned long long g_tab[TABLE_SIZE];   // zero-init: gen 0 = stale
__device__ unsigned long long g_ctr_ins;           // insert-kernel call counter
__device__ unsigned long long g_ctr_lkp;           // lookup-kernel call counter

__device__ __forceinline__ uint32_t hash_key(uint32_t key) {
    return (key * 0x9E3779B1u) >> (32 - TABLE_LOG2);
}

__device__ __forceinline__ unsigned long long
block_gen(unsigned long long* ctr) {
    __shared__ unsigned long long s_gen;
    if (threadIdx.x == 0) {
        unsigned long long t = atomicAdd(ctr, 1ull);
        s_gen = t / gridDim.x + 1ull;     // same value for every block of a call
    }
    __syncthreads();
    return s_gen;
}

// ---- Kernel 1: insert old edges --------------------------------------------
__global__ void insert_kernel(const int* __restrict__ edge_index_old,
                              int E_old, int total_nodes) {
    const unsigned long long gen = block_gen(&g_ctr_ins);
    int i = blockIdx.x * blockDim.x + threadIdx.x;
    if (i >= E_old) return;

    uint32_t key = (uint32_t)(__ldg(edge_index_old + i) * total_nodes
                              + __ldg(edge_index_old + E_old + i));
    const unsigned long long word =
        (gen << GEN_SHIFT) | ((unsigned long long)key << KEY_SHIFT)
        | (unsigned long long)(uint32_t)i;
    const unsigned long long tag = (gen << GEN_SHIFT)
        | ((unsigned long long)key << KEY_SHIFT);     // gen|key, idx=0

    uint32_t h = hash_key(key);
    unsigned long long w = g_tab[h];
    while (true) {
        if ((w >> GEN_SHIFT) != gen) {
            // Stale slot -> try to claim it (value rides along).
            unsigned long long prev = atomicCAS(&g_tab[h], w, word);
            if (prev == w) break;
            w = prev;                       // re-examine what beat us
        } else if ((w >> KEY_SHIFT) == (tag >> KEY_SHIFT)) {
            // Same gen, same key -> max idx wins.
            atomicMax(&g_tab[h], word);
            break;
        } else {
            // Same gen, different key -> linear probe.
            h = (h + 1) & TABLE_MASK;
            w = g_tab[h];
        }
    }
}

// ---- Kernel 2: lookup new edges, gather, emit [E_new, 8] -------------------
__global__ void lookup_emit_kernel(const int*   __restrict__ edge_index_new,
                                   const float* __restrict__ edge_attr_old,
                                   const float* __restrict__ flow_old,
                                   const float* __restrict__ edge_attr_new,
                                   float*       __restrict__ out,
                                   int E_new, int total_nodes) {
    const unsigned long long gen = block_gen(&g_ctr_lkp);
    int i = blockIdx.x * blockDim.x + threadIdx.x;
    if (i >= E_new) return;

    uint32_t key = (uint32_t)(__ldg(edge_index_new + i) * total_nodes
                              + __ldg(edge_index_new + E_new + i));
    const unsigned long long tag =
        (gen << GEN_SHIFT) | ((unsigned long long)key << KEY_SHIFT);

    int match = -1;
    uint32_t h = hash_key(key);
    while (true) {
        unsigned long long w = __ldg(&g_tab[h]);
        if ((w >> KEY_SHIFT) == (tag >> KEY_SHIFT) && (w >> GEN_SHIFT) == gen) {
            match = (int)(w & IDX_MASK);
            break;
        }
        if ((w >> GEN_SHIFT) != gen) break;   // stale == empty: not present
        h = (h + 1) & TABLE_MASK;             // same gen, other key: probe on
    }

    float a0 = 0.f, a1 = 0.f, a2 = 0.f, a3 = 0.f;
    float flag = 1.f;  // is_new_edge
    if (match >= 0) {
        const float* ea = edge_attr_old + (size_t)match * 3;
        a0 = __ldg(ea + 0);
        a1 = __ldg(ea + 1);
        a2 = __ldg(ea + 2);
        a3 = __ldg(flow_old + match);
        flag = 0.f;
    }
    const float* en = edge_attr_new + (size_t)i * 3;
    float n0 = __ldg(en + 0), n1 = __ldg(en + 1), n2 = __ldg(en + 2);

    float4* o = reinterpret_cast<float4*>(out + (size_t)i * 8);
    o[0] = make_float4(a0, a1, a2, a3);
    o[1] = make_float4(n0, n1, n2, flag);
}

extern "C" void kernel_launch(void* const* d_in, const int* in_sizes, int n_in,
                              void* d_out, int out_size) {
    const int*   edge_index_old = (const int*)  d_in[0];
    const float* edge_attr_old  = (const float*)d_in[1];
    const float* flow_old       = (const float*)d_in[2];
    const int*   edge_index_new = (const int*)  d_in[3];
    const float* edge_attr_new  = (const float*)d_in[4];
    (void)n_in; (void)out_size;

    int E_old = in_sizes[1] / 3;   // edge_attr_old is [E_old, 3]
    int E_new = in_sizes[4] / 3;   // edge_attr_new is [E_new, 3]
    int total_nodes = 10000;       // fixed by problem; key fits in 27 bits

    int threads = 256;
    insert_kernel<<<(E_old + threads - 1) / threads, threads>>>(
        edge_index_old, E_old, total_nodes);
    lookup_emit_kernel<<<(E_new + threads - 1) / threads, threads>>>(
        edge_index_new, edge_attr_old, flow_old, edge_attr_new,
        (float*)d_out, E_new, total_nodes);
}